// round 1
// baseline (speedup 1.0000x reference)
#include <cuda_runtime.h>
#include <cstdint>

// C4ByteNibbleVM: the reference is a soft-lookup "neural VM" on exact one-hot
// bytes. Semantics: s = (a + b) mod 2^32 (little-endian ripple carry), then
// out_byte[i] = s_byte[i] ^ a_byte[i], emitted as one-hot [B,4,256] float32.
// Softmax temperature in the reference makes its output one-hot to ~1e-7, so
// exact integer computation + exact one-hot output is within rel_err 1e-3.
//
// One warp per word. Lane l handles float4 #l and #(l+32) of each 256-float
// row (fully coalesced 128-bit accesses). Decode: since each row has exactly
// one 1.0, sum over lanes of (global_index * (v > 0.5)) gives the index.

__global__ __launch_bounds__(256) void c4_vm_kernel(
    const float* __restrict__ a,
    const float* __restrict__ b,
    float* __restrict__ out,
    int nwords)
{
    const int warp = (blockIdx.x * (blockDim.x >> 5)) + (threadIdx.x >> 5);
    const int lane = threadIdx.x & 31;
    if (warp >= nwords) return;

    const float4* __restrict__ a4 = reinterpret_cast<const float4*>(a) + (size_t)warp * 256;
    const float4* __restrict__ b4 = reinterpret_cast<const float4*>(b) + (size_t)warp * 256;

    unsigned av = 0, bv = 0;

#pragma unroll
    for (int i = 0; i < 4; i++) {
        // a-row i
        float4 v0 = a4[i * 64 + lane];
        float4 v1 = a4[i * 64 + 32 + lane];
        unsigned loc = 0;
        int base0 = lane * 4, base1 = 128 + lane * 4;
        if (v0.x > 0.5f) loc += base0 + 0;
        if (v0.y > 0.5f) loc += base0 + 1;
        if (v0.z > 0.5f) loc += base0 + 2;
        if (v0.w > 0.5f) loc += base0 + 3;
        if (v1.x > 0.5f) loc += base1 + 0;
        if (v1.y > 0.5f) loc += base1 + 1;
        if (v1.z > 0.5f) loc += base1 + 2;
        if (v1.w > 0.5f) loc += base1 + 3;
        unsigned ai = __reduce_add_sync(0xffffffffu, loc);
        av |= (ai & 0xffu) << (8 * i);

        // b-row i
        float4 w0 = b4[i * 64 + lane];
        float4 w1 = b4[i * 64 + 32 + lane];
        loc = 0;
        if (w0.x > 0.5f) loc += base0 + 0;
        if (w0.y > 0.5f) loc += base0 + 1;
        if (w0.z > 0.5f) loc += base0 + 2;
        if (w0.w > 0.5f) loc += base0 + 3;
        if (w1.x > 0.5f) loc += base1 + 0;
        if (w1.y > 0.5f) loc += base1 + 1;
        if (w1.z > 0.5f) loc += base1 + 2;
        if (w1.w > 0.5f) loc += base1 + 3;
        unsigned bi = __reduce_add_sync(0xffffffffu, loc);
        bv |= (bi & 0xffu) << (8 * i);
    }

    const unsigned s = av + bv;      // 32-bit ripple-carry add, byte 0 = LSB
    const unsigned o = s ^ av;       // chained XOR op, per byte

    float4* __restrict__ o4 = reinterpret_cast<float4*>(out) + (size_t)warp * 256;

#pragma unroll
    for (int i = 0; i < 4; i++) {
        const unsigned ob = (o >> (8 * i)) & 0xffu;
        const int q = ob >> 2;       // which float4 (0..63)
        const int e = ob & 3;        // element within float4
        float4 z0 = make_float4(0.f, 0.f, 0.f, 0.f);
        float4 z1 = make_float4(0.f, 0.f, 0.f, 0.f);
        if (q == lane)       (&z0.x)[e] = 1.0f;
        if (q == lane + 32)  (&z1.x)[e] = 1.0f;
        o4[i * 64 + lane] = z0;
        o4[i * 64 + 32 + lane] = z1;
    }
}

extern "C" void kernel_launch(void* const* d_in, const int* in_sizes, int n_in,
                              void* d_out, int out_size)
{
    const float* a = (const float*)d_in[0];   // a_bytes [B,4,256]
    const float* b = (const float*)d_in[1];   // b_bytes [B,4,256]
    float* out = (float*)d_out;               // [B,4,256]

    const int nwords = in_sizes[0] / 1024;    // B
    const int warps_per_block = 8;            // 256 threads
    const int blocks = (nwords + warps_per_block - 1) / warps_per_block;

    c4_vm_kernel<<<blocks, 256>>>(a, b, out, nwords);
}